// round 1
// baseline (speedup 1.0000x reference)
#include <cuda_runtime.h>
#include <math.h>

// Problem constants
#define Bb 4
#define Ss 2048
#define Dd 1024
#define Hh 4096
#define MM (Bb * Ss)   // 8192 rows (b,s flattened)

// Scratch (device globals — allocation-free rule)
__device__ float g_h[(size_t)MM * Hh];   // post-GELU hidden, 134 MB
__device__ float g_U1[MM * 4];           // rank-4 lora-1 coefficients
__device__ float g_V[MM * 16];           // rank-16 lora-2 coefficients

__device__ __forceinline__ float gelu_exact(float v) {
    return 0.5f * v * (1.0f + erff(v * 0.70710678118654752f));
}

// ---------------------------------------------------------------------------
// U1[b,s,r] = x[b,s,:] . x[b, 2+2r, :]   (odd1 tokens 2,4,6,8)
// one warp per (b,s)
// ---------------------------------------------------------------------------
__global__ void u1_kernel(const float* __restrict__ x) {
    int gw = (blockIdx.x * blockDim.x + threadIdx.x) >> 5;
    int lane = threadIdx.x & 31;
    if (gw >= MM) return;
    int b = gw >> 11;
    const float4* xr = (const float4*)(x + (size_t)gw * Dd);
    const float4* o0 = (const float4*)(x + ((size_t)b * Ss + 2) * Dd);
    const float4* o1 = (const float4*)(x + ((size_t)b * Ss + 4) * Dd);
    const float4* o2 = (const float4*)(x + ((size_t)b * Ss + 6) * Dd);
    const float4* o3 = (const float4*)(x + ((size_t)b * Ss + 8) * Dd);
    float a0 = 0.f, a1 = 0.f, a2 = 0.f, a3 = 0.f;
    for (int j = lane; j < Dd / 4; j += 32) {
        float4 xv = xr[j];
        float4 v;
        v = o0[j]; a0 += xv.x * v.x + xv.y * v.y + xv.z * v.z + xv.w * v.w;
        v = o1[j]; a1 += xv.x * v.x + xv.y * v.y + xv.z * v.z + xv.w * v.w;
        v = o2[j]; a2 += xv.x * v.x + xv.y * v.y + xv.z * v.z + xv.w * v.w;
        v = o3[j]; a3 += xv.x * v.x + xv.y * v.y + xv.z * v.z + xv.w * v.w;
    }
    #pragma unroll
    for (int off = 16; off; off >>= 1) {
        a0 += __shfl_xor_sync(0xFFFFFFFFu, a0, off);
        a1 += __shfl_xor_sync(0xFFFFFFFFu, a1, off);
        a2 += __shfl_xor_sync(0xFFFFFFFFu, a2, off);
        a3 += __shfl_xor_sync(0xFFFFFFFFu, a3, off);
    }
    if (lane == 0) {
        g_U1[gw * 4 + 0] = a0;
        g_U1[gw * 4 + 1] = a1;
        g_U1[gw * 4 + 2] = a2;
        g_U1[gw * 4 + 3] = a3;
    }
}

// ---------------------------------------------------------------------------
// V[b,s,r,k] = sum_j h[b,s, k*1024+j] * x[b, 10+2r, j]   (odd2 tokens 10..16)
// one warp per (b,s); runs after gemm1 fills g_h
// ---------------------------------------------------------------------------
__global__ void v_kernel(const float* __restrict__ x) {
    int gw = (blockIdx.x * blockDim.x + threadIdx.x) >> 5;
    int lane = threadIdx.x & 31;
    if (gw >= MM) return;
    int b = gw >> 11;
    const float4* od[4];
    #pragma unroll
    for (int r = 0; r < 4; r++)
        od[r] = (const float4*)(x + ((size_t)b * Ss + 10 + 2 * r) * Dd);
    float acc[16];
    #pragma unroll
    for (int i = 0; i < 16; i++) acc[i] = 0.f;
    #pragma unroll
    for (int k = 0; k < 4; k++) {
        const float4* hr = (const float4*)(g_h + (size_t)gw * Hh + k * 1024);
        for (int j = lane; j < 256; j += 32) {
            float4 hv = hr[j];
            #pragma unroll
            for (int r = 0; r < 4; r++) {
                float4 ov = od[r][j];
                acc[r * 4 + k] += hv.x * ov.x + hv.y * ov.y + hv.z * ov.z + hv.w * ov.w;
            }
        }
    }
    #pragma unroll
    for (int i = 0; i < 16; i++) {
        #pragma unroll
        for (int off = 16; off; off >>= 1)
            acc[i] += __shfl_xor_sync(0xFFFFFFFFu, acc[i], off);
    }
    if (lane == 0) {
        #pragma unroll
        for (int i = 0; i < 16; i++) g_V[gw * 16 + i] = acc[i];
    }
}

// ---------------------------------------------------------------------------
// GEMM1: h = gelu(x @ W1^T + scale * lora1 + b1)
// M=8192, N=4096, K=1024.  A row-major (K contig), B row-major (K contig).
// BM=BN=128, BK=16, 256 threads, 8x8 per thread, warp tile 32x64.
// ---------------------------------------------------------------------------
__global__ __launch_bounds__(256, 2)
void gemm1_kernel(const float* __restrict__ A,
                  const float* __restrict__ Wt,
                  const float* __restrict__ bias,
                  const float* __restrict__ scale_p)
{
    const int K = Dd;  // 1024
    __shared__ float As[16][128];
    __shared__ float Bs[16][128];

    int tid  = threadIdx.x;
    int m0   = blockIdx.y * 128;
    int n0   = blockIdx.x * 128;
    int lane = tid & 31, warp = tid >> 5;
    int wm = warp >> 1, wn = warp & 1;      // 4 x 2 warp grid
    int lm = lane >> 3, ln = lane & 7;      // 4 x 8 lane grid
    int row_a = tid & 127;                  // tile row this thread loads
    int qa    = tid >> 7;                   // 0..1 (also qa+2)

    const float4* Ag = (const float4*)(A  + (size_t)(m0 + row_a) * K);
    const float4* Bg = (const float4*)(Wt + (size_t)(n0 + row_a) * K);

    float acc[8][8];
    #pragma unroll
    for (int i = 0; i < 8; i++)
        #pragma unroll
        for (int j = 0; j < 8; j++) acc[i][j] = 0.f;

    float4 pa0 = Ag[qa], pa1 = Ag[qa + 2];
    float4 pb0 = Bg[qa], pb1 = Bg[qa + 2];

    const int nk = K / 16;
    for (int t = 1; t <= nk; ++t) {
        // store current staged tile
        As[qa * 4 + 0][row_a] = pa0.x; As[qa * 4 + 1][row_a] = pa0.y;
        As[qa * 4 + 2][row_a] = pa0.z; As[qa * 4 + 3][row_a] = pa0.w;
        As[qa * 4 + 8][row_a] = pa1.x; As[qa * 4 + 9][row_a] = pa1.y;
        As[qa * 4 + 10][row_a] = pa1.z; As[qa * 4 + 11][row_a] = pa1.w;
        Bs[qa * 4 + 0][row_a] = pb0.x; Bs[qa * 4 + 1][row_a] = pb0.y;
        Bs[qa * 4 + 2][row_a] = pb0.z; Bs[qa * 4 + 3][row_a] = pb0.w;
        Bs[qa * 4 + 8][row_a] = pb1.x; Bs[qa * 4 + 9][row_a] = pb1.y;
        Bs[qa * 4 + 10][row_a] = pb1.z; Bs[qa * 4 + 11][row_a] = pb1.w;
        __syncthreads();

        if (t < nk) {   // prefetch next tile (overlaps compute below)
            int kq = t * 4;
            pa0 = Ag[kq + qa]; pa1 = Ag[kq + qa + 2];
            pb0 = Bg[kq + qa]; pb1 = Bg[kq + qa + 2];
        }

        #pragma unroll
        for (int k = 0; k < 16; ++k) {
            float a[8], bq[8];
            *(float4*)&a[0]  = *(const float4*)&As[k][wm * 32 + lm * 8];
            *(float4*)&a[4]  = *(const float4*)&As[k][wm * 32 + lm * 8 + 4];
            *(float4*)&bq[0] = *(const float4*)&Bs[k][wn * 64 + ln * 8];
            *(float4*)&bq[4] = *(const float4*)&Bs[k][wn * 64 + ln * 8 + 4];
            #pragma unroll
            for (int i = 0; i < 8; i++)
                #pragma unroll
                for (int j = 0; j < 8; j++)
                    acc[i][j] += a[i] * bq[j];
        }
        __syncthreads();
    }

    // epilogue: + scale*U1[m,r]*even1[b,r,i] + b1, gelu, store to g_h
    float sc = *scale_p;
    int col0 = n0 + wn * 64 + ln * 8;
    int r    = col0 >> 10;       // constant across the 8 cols (8-aligned)
    int ci   = col0 & 1023;
    #pragma unroll
    for (int i = 0; i < 8; i++) {
        int m = m0 + wm * 32 + lm * 8 + i;
        int b = m >> 11;
        float u = sc * g_U1[m * 4 + r];
        const float* ev = A + ((size_t)b * Ss + 1 + 2 * r) * Dd + ci;  // even1 token 1+2r
        float* hdst = g_h + (size_t)m * Hh + col0;
        #pragma unroll
        for (int j = 0; j < 8; j++) {
            float c = acc[i][j] + u * ev[j] + bias[col0 + j];
            hdst[j] = gelu_exact(c);
        }
    }
}

// ---------------------------------------------------------------------------
// GEMM2: out = h @ W2^T + scale * lora2 + b2
// M=8192, N=1024, K=4096
// ---------------------------------------------------------------------------
__global__ __launch_bounds__(256, 2)
void gemm2_kernel(const float* __restrict__ Wt,     // W2: 1024 x 4096
                  const float* __restrict__ bias,
                  const float* __restrict__ x,      // for even2 vectors
                  const float* __restrict__ scale_p,
                  float* __restrict__ out)
{
    const int K = Hh;  // 4096
    __shared__ float As[16][128];
    __shared__ float Bs[16][128];

    int tid  = threadIdx.x;
    int m0   = blockIdx.y * 128;
    int n0   = blockIdx.x * 128;
    int lane = tid & 31, warp = tid >> 5;
    int wm = warp >> 1, wn = warp & 1;
    int lm = lane >> 3, ln = lane & 7;
    int row_a = tid & 127;
    int qa    = tid >> 7;

    const float4* Ag = (const float4*)(g_h + (size_t)(m0 + row_a) * K);
    const float4* Bg = (const float4*)(Wt  + (size_t)(n0 + row_a) * K);

    float acc[8][8];
    #pragma unroll
    for (int i = 0; i < 8; i++)
        #pragma unroll
        for (int j = 0; j < 8; j++) acc[i][j] = 0.f;

    float4 pa0 = Ag[qa], pa1 = Ag[qa + 2];
    float4 pb0 = Bg[qa], pb1 = Bg[qa + 2];

    const int nk = K / 16;
    for (int t = 1; t <= nk; ++t) {
        As[qa * 4 + 0][row_a] = pa0.x; As[qa * 4 + 1][row_a] = pa0.y;
        As[qa * 4 + 2][row_a] = pa0.z; As[qa * 4 + 3][row_a] = pa0.w;
        As[qa * 4 + 8][row_a] = pa1.x; As[qa * 4 + 9][row_a] = pa1.y;
        As[qa * 4 + 10][row_a] = pa1.z; As[qa * 4 + 11][row_a] = pa1.w;
        Bs[qa * 4 + 0][row_a] = pb0.x; Bs[qa * 4 + 1][row_a] = pb0.y;
        Bs[qa * 4 + 2][row_a] = pb0.z; Bs[qa * 4 + 3][row_a] = pb0.w;
        Bs[qa * 4 + 8][row_a] = pb1.x; Bs[qa * 4 + 9][row_a] = pb1.y;
        Bs[qa * 4 + 10][row_a] = pb1.z; Bs[qa * 4 + 11][row_a] = pb1.w;
        __syncthreads();

        if (t < nk) {
            int kq = t * 4;
            pa0 = Ag[kq + qa]; pa1 = Ag[kq + qa + 2];
            pb0 = Bg[kq + qa]; pb1 = Bg[kq + qa + 2];
        }

        #pragma unroll
        for (int k = 0; k < 16; ++k) {
            float a[8], bq[8];
            *(float4*)&a[0]  = *(const float4*)&As[k][wm * 32 + lm * 8];
            *(float4*)&a[4]  = *(const float4*)&As[k][wm * 32 + lm * 8 + 4];
            *(float4*)&bq[0] = *(const float4*)&Bs[k][wn * 64 + ln * 8];
            *(float4*)&bq[4] = *(const float4*)&Bs[k][wn * 64 + ln * 8 + 4];
            #pragma unroll
            for (int i = 0; i < 8; i++)
                #pragma unroll
                for (int j = 0; j < 8; j++)
                    acc[i][j] += a[i] * bq[j];
        }
        __syncthreads();
    }

    // epilogue: + scale * sum_k even2[b, r, (n&255)*4+k] * V[m, r, k] + b2
    float sc = *scale_p;
    int col0 = n0 + wn * 64 + ln * 8;
    int r    = col0 >> 8;    // constant across 8 cols
    #pragma unroll
    for (int i = 0; i < 8; i++) {
        int m = m0 + wm * 32 + lm * 8 + i;
        int b = m >> 11;
        float4 vv = *(const float4*)&g_V[m * 16 + r * 4];
        const float4* ev2 = (const float4*)(x + ((size_t)b * Ss + 9 + 2 * r) * Dd); // even2 token 9+2r
        float* od = out + (size_t)m * Dd + col0;
        #pragma unroll
        for (int j = 0; j < 8; j++) {
            int n = col0 + j;
            float4 e = ev2[n & 255];
            float lora = vv.x * e.x + vv.y * e.y + vv.z * e.z + vv.w * e.w;
            od[j] = acc[i][j] + sc * lora + bias[n];
        }
    }
}

// ---------------------------------------------------------------------------
extern "C" void kernel_launch(void* const* d_in, const int* in_sizes, int n_in,
                              void* d_out, int out_size) {
    const float* x     = (const float*)d_in[0];
    const float* W1    = (const float*)d_in[1];
    const float* b1    = (const float*)d_in[2];
    const float* W2    = (const float*)d_in[3];
    const float* b2    = (const float*)d_in[4];
    const float* scale = (const float*)d_in[5];
    float* out = (float*)d_out;

    // U1 (rank-4 coefficients for layer 1)
    u1_kernel<<<MM / 8, 256>>>(x);

    // h = gelu(x @ W1^T + lora1 + b1)
    dim3 g1(Hh / 128, MM / 128);   // (32, 64)
    gemm1_kernel<<<g1, 256>>>(x, W1, b1, scale);

    // V (rank-16 coefficients for layer 2)
    v_kernel<<<MM / 8, 256>>>(x);

    // out = h @ W2^T + lora2 + b2
    dim3 g2(Dd / 128, MM / 128);   // (8, 64)
    gemm2_kernel<<<g2, 256>>>(W2, b2, x, scale, out);
}